// round 12
// baseline (speedup 1.0000x reference)
#include <cuda_runtime.h>
#include <cuda_fp16.h>
#include <cstdint>

// ============================================================
// Problem constants
// ============================================================
#define BN   4
#define CN   16
#define HN   512
#define WN   512
#define TILE 128      // pixels per row-tile; tile = 2 rows x 128 px = 256 M-rows
#define NT   8        // row-pair tiles per CTA

// SMEM layout (byte offsets). Total 113664 B -> 2 CTAs/SM.
#define SM_RING  0            // x ring: 6 slots x 16 ch x 128 px f32 = 49152
#define RING_SLOT_F 2048      // floats per ring slot
#define SM_A     49152        // A: 256 rows x 112 B (f16 x 48) = 28672
#define PITCH_A  112
#define SM_UPD   77824        // update stage: 16 ch x 260 f32 = 16640
#define UPD_PITCH 260
#define SM_W0    94464        // w0: 128 rows x 112 B = 14336
#define PITCH_W0 112
#define SM_W1    108800       // w1: 16 rows x 272 B = 4352
#define PITCH_W1 272
#define SM_BIAS  113152       // b0: 128 f32 = 512
#define SM_TOTAL 113664

// ============================================================
// PTX helpers (base sm_103-compatible: ldmatrix + mma.sync + cp.async)
// ============================================================
__device__ __forceinline__ uint32_t smem_u32(const void* p) {
    uint32_t a;
    asm("{ .reg .u64 t; cvta.to.shared.u64 t, %1; cvt.u32.u64 %0, t; }"
        : "=r"(a) : "l"(p));
    return a;
}

__device__ __forceinline__ void ldsm_x4(uint32_t* r, uint32_t addr) {
    asm volatile("ldmatrix.sync.aligned.m8n8.x4.shared.b16 {%0,%1,%2,%3}, [%4];"
                 : "=r"(r[0]), "=r"(r[1]), "=r"(r[2]), "=r"(r[3]) : "r"(addr));
}

// D += A * B  (m16n8k16, f16 in, f32 accum)
__device__ __forceinline__ void mma16816(float* c, const uint32_t* a,
                                         uint32_t b0, uint32_t b1) {
    asm volatile("mma.sync.aligned.m16n8k16.row.col.f32.f16.f16.f32 "
                 "{%0,%1,%2,%3}, {%4,%5,%6,%7}, {%8,%9}, {%0,%1,%2,%3};"
                 : "+f"(c[0]), "+f"(c[1]), "+f"(c[2]), "+f"(c[3])
                 : "r"(a[0]), "r"(a[1]), "r"(a[2]), "r"(a[3]),
                   "r"(b0), "r"(b1));
}

// D = A * B + {cx,cy,cx,cy}  (bias injected via C operand)
__device__ __forceinline__ void mma16816_init(float* d, const uint32_t* a,
                                              uint32_t b0, uint32_t b1,
                                              float cx, float cy) {
    asm volatile("mma.sync.aligned.m16n8k16.row.col.f32.f16.f16.f32 "
                 "{%0,%1,%2,%3}, {%4,%5,%6,%7}, {%8,%9}, {%10,%11,%10,%11};"
                 : "=&f"(d[0]), "=&f"(d[1]), "=&f"(d[2]), "=&f"(d[3])
                 : "r"(a[0]), "r"(a[1]), "r"(a[2]), "r"(a[3]),
                   "r"(b0), "r"(b1), "f"(cx), "f"(cy));
}

__device__ __forceinline__ uint32_t pack2(float a, float b) {
    __half2 h = __floats2half2_rn(a, b);
    return *reinterpret_cast<uint32_t*>(&h);
}

__device__ __forceinline__ uint32_t packrelu2(float a, float b) {
    __half2 h = __floats2half2_rn(a, b);
    h = __hmax2(h, __half2half2(__ushort_as_half(0)));
    return *reinterpret_cast<uint32_t*>(&h);
}

#define CP_COMMIT() asm volatile("cp.async.commit_group;" ::: "memory")
#define CP_WAIT1()  asm volatile("cp.async.wait_group 1;" ::: "memory")

// Prefetch 2 image rows (row0, row0+1) of the 128-px tile column into the
// ring (slot = row mod 6). Out-of-image rows are zero-filled via STS.
__device__ __forceinline__ void prefetch2(const float* __restrict__ x, char* smem,
                                          int row0, int bb, int wpix, int tid) {
    #pragma unroll
    for (int k = 0; k < 4; k++) {
        const int ci  = tid + (k << 8);
        const int rr  = ci >> 9;            // row within pair
        const int ch  = (ci >> 5) & 15;     // channel
        const int seg = ci & 31;            // 16B segment
        const int row = row0 + rr;
        const int slot = (row + 6) % 6;
        float* dst = reinterpret_cast<float*>(smem + SM_RING)
                     + slot * RING_SLOT_F + ch * 128 + seg * 4;
        if ((unsigned)row < (unsigned)HN) {
            const float* src = x + (((size_t)bb * CN + ch) * HN + row) * WN
                               + wpix + seg * 4;
            asm volatile("cp.async.cg.shared.global [%0], [%1], 16;"
                         :: "r"(smem_u32(dst)), "l"(src) : "memory");
        } else {
            *reinterpret_cast<float4*>(dst) = make_float4(0.f, 0.f, 0.f, 0.f);
        }
    }
}

// ============================================================
// Kernel: one CTA = NT consecutive row-pairs x 128 px, pipelined:
//   cp.async prefetches x rows 2 tiles ahead into a 6-slot SMEM ring;
//   phase1 (Sobel) reads the ring (LDS), phase2 = fused MLP (mma.sync),
//   phase3 = vectorized epilogue with x residual from the ring.
// ============================================================
__global__ void __launch_bounds__(256, 2) ca_mlp_kernel(
    const float* __restrict__ x,
    const float* __restrict__ w0,
    const float* __restrict__ b0,
    const float* __restrict__ w1,
    const float* __restrict__ ru,
    float* __restrict__ out)
{
    extern __shared__ char smem[];
    const uint32_t sbase = smem_u32(smem);
    float* ring = reinterpret_cast<float*>(smem + SM_RING);

    const int tid  = threadIdx.x;
    const int warp = tid >> 5;
    const int lane = tid & 31;

    const int bx     = blockIdx.x;
    const int wt     = bx & 3;               // column tile
    const int hgroup = (bx >> 2) & 31;       // group of NT row pairs
    const int bb     = bx >> 7;              // batch
    const int hstart = hgroup * (2 * NT);
    const int wpix   = wt * TILE;

    // ---------------- Prologue: prefetch window(0) + window(1)'s new rows ----------------
    prefetch2(x, smem, hstart - 1, bb, wpix, tid);
    prefetch2(x, smem, hstart + 1, bb, wpix, tid);
    CP_COMMIT();                               // G0: rows hstart-1 .. hstart+2
    prefetch2(x, smem, hstart + 3, bb, wpix, tid);
    CP_COMMIT();                               // G1: rows hstart+3, hstart+4

    // ---------------- Load weights / bias to SMEM (amortized over NT tiles) ----------------
    for (int idx = tid; idx < 128 * 24; idx += 256) {
        const int o = idx / 24;
        const int k = (idx - o * 24) * 2;
        *reinterpret_cast<uint32_t*>(smem + SM_W0 + o * PITCH_W0 + k * 2) =
            pack2(w0[o * 48 + k], w0[o * 48 + k + 1]);
    }
    for (int idx = tid; idx < 16 * 64; idx += 256) {
        const int o = idx >> 6;
        const int k = (idx & 63) * 2;
        *reinterpret_cast<uint32_t*>(smem + SM_W1 + o * PITCH_W1 + k * 2) =
            pack2(w1[o * 128 + k], w1[o * 128 + k + 1]);
    }
    if (tid < 128)
        *reinterpret_cast<float*>(smem + SM_BIAS + tid * 4) = b0[tid];

    // ================= Tile loop =================
    for (int it = 0; it < NT; it++) {
        const int h0 = hstart + 2 * it;

        CP_WAIT1();          // this tile's window rows resident
        __syncthreads();     // ring + A/upd from previous tile quiesced

        // ---------------- Phase 1: Sobel from ring -> SMEM A ----------------
        {
            const int g8   = tid >> 7;
            const int pcol = tid & 127;
            const int c0   = g8 * 8;
            const int s0 = (h0 + 5) % 6;     // row h0-1
            const int s1 = (h0    ) % 6;
            const int s2 = (h0 + 1) % 6;
            const int s3 = (h0 + 2) % 6;

            const bool isL = (lane == 0);
            const bool isR = (lane == 31);
            const int  pe  = isL ? pcol - 1 : pcol + 1;
            const bool peIn = (isL || isR) && ((unsigned)pe < 128u);
            const int  Pe  = wpix + pe;
            const bool peG = (isL || isR) && !peIn && ((unsigned)Pe < (unsigned)WN);
            const bool r0ok = (h0 - 1) >= 0;
            const bool r3ok = (h0 + 2) < HN;

            uint32_t ft[3][4], fb[3][4];

            #pragma unroll
            for (int cp = 0; cp < 4; cp++) {
                float xvt[2], xvb[2], gxt[2], gxb[2], gyt[2], gyb[2];
                #pragma unroll
                for (int e = 0; e < 2; e++) {
                    const int c = c0 + cp * 2 + e;
                    const float* rc = ring + c * 128 + pcol;
                    const float x0 = rc[s0 * RING_SLOT_F];
                    const float x1 = rc[s1 * RING_SLOT_F];
                    const float x2 = rc[s2 * RING_SLOT_F];
                    const float x3 = rc[s3 * RING_SLOT_F];

                    const float sv0 = x0 + 2.0f * x1 + x2;
                    const float sv1 = x1 + 2.0f * x2 + x3;
                    const float dv0 = x2 - x0;
                    const float dv1 = x3 - x1;

                    float se0 = 0.f, se1 = 0.f, de0 = 0.f, de1 = 0.f;
                    if (peIn) {            // interior warp boundary: ring LDS
                        const float* re = ring + c * 128 + pe;
                        const float e0 = re[s0 * RING_SLOT_F];
                        const float e1 = re[s1 * RING_SLOT_F];
                        const float e2 = re[s2 * RING_SLOT_F];
                        const float e3 = re[s3 * RING_SLOT_F];
                        se0 = e0 + 2.0f * e1 + e2;
                        se1 = e1 + 2.0f * e2 + e3;
                        de0 = e2 - e0;
                        de1 = e3 - e1;
                    } else if (peG) {      // true tile edge: gmem
                        const float* ecol = x + (((size_t)bb * CN + c) * HN
                                                 + (h0 - 1)) * WN + Pe;
                        const float e0 = r0ok ? ecol[0]      : 0.f;
                        const float e1 =        ecol[WN];
                        const float e2 =        ecol[2 * WN];
                        const float e3 = r3ok ? ecol[3 * WN] : 0.f;
                        se0 = e0 + 2.0f * e1 + e2;
                        se1 = e1 + 2.0f * e2 + e3;
                        de0 = e2 - e0;
                        de1 = e3 - e1;
                    }

                    float sl0 = __shfl_up_sync(0xffffffffu, sv0, 1);
                    float sl1 = __shfl_up_sync(0xffffffffu, sv1, 1);
                    float dl0 = __shfl_up_sync(0xffffffffu, dv0, 1);
                    float dl1 = __shfl_up_sync(0xffffffffu, dv1, 1);
                    float sr0 = __shfl_down_sync(0xffffffffu, sv0, 1);
                    float sr1 = __shfl_down_sync(0xffffffffu, sv1, 1);
                    float dr0 = __shfl_down_sync(0xffffffffu, dv0, 1);
                    float dr1 = __shfl_down_sync(0xffffffffu, dv1, 1);
                    if (isL) { sl0 = se0; sl1 = se1; dl0 = de0; dl1 = de1; }
                    if (isR) { sr0 = se0; sr1 = se1; dr0 = de0; dr1 = de1; }

                    xvt[e] = x1;
                    xvb[e] = x2;
                    gxt[e] = sr0 - sl0;
                    gxb[e] = sr1 - sl1;
                    gyt[e] = dl0 + 2.0f * dv0 + dr0;
                    gyb[e] = dl1 + 2.0f * dv1 + dr1;
                }
                ft[0][cp] = pack2(xvt[0], xvt[1]);
                ft[1][cp] = pack2(gxt[0], gxt[1]);
                ft[2][cp] = pack2(gyt[0], gyt[1]);
                fb[0][cp] = pack2(xvb[0], xvb[1]);
                fb[1][cp] = pack2(gxb[0], gxb[1]);
                fb[2][cp] = pack2(gyb[0], gyb[1]);
            }

            char* rowt = smem + SM_A + pcol * PITCH_A;
            char* rowb = smem + SM_A + (128 + pcol) * PITCH_A;
            #pragma unroll
            for (int f = 0; f < 3; f++) {
                *reinterpret_cast<uint4*>(rowt + f * 32 + c0 * 2) =
                    make_uint4(ft[f][0], ft[f][1], ft[f][2], ft[f][3]);
                *reinterpret_cast<uint4*>(rowb + f * 32 + c0 * 2) =
                    make_uint4(fb[f][0], fb[f][1], fb[f][2], fb[f][3]);
            }
        }
        __syncthreads();   // A ready

        // ---------------- Phase 2: fused MLP (per warp: 32 M-rows) ----------------
        {
            const int m0 = warp * 32;
            const int t  = lane & 3;
            const int g  = lane >> 2;

            uint32_t afr[3][2][4];
            #pragma unroll
            for (int kt = 0; kt < 3; kt++) {
                const uint32_t acol = kt * 32 + ((lane >> 4) << 4);
                ldsm_x4(afr[kt][0], sbase + SM_A + (m0 + (lane & 15)) * PITCH_A + acol);
                ldsm_x4(afr[kt][1], sbase + SM_A + (m0 + 16 + (lane & 15)) * PITCH_A + acol);
            }

            float c2[2][2][4];
            #pragma unroll
            for (int mt = 0; mt < 2; mt++)
                #pragma unroll
                for (int n2 = 0; n2 < 2; n2++)
                    #pragma unroll
                    for (int j = 0; j < 4; j++) c2[mt][n2][j] = 0.0f;

            #pragma unroll
            for (int hcj = 0; hcj < 8; hcj++) {
                const float2 bA = *reinterpret_cast<const float2*>(
                    smem + SM_BIAS + (hcj * 16 + t * 2) * 4);
                const float2 bB = *reinterpret_cast<const float2*>(
                    smem + SM_BIAS + (hcj * 16 + 8 + t * 2) * 4);

                float c1[2][2][4];
                {
                    uint32_t bfr[4];
                    ldsm_x4(bfr, sbase + SM_W0 + (hcj * 16 + (lane & 15)) * PITCH_W0
                                 + ((lane >> 4) << 4));
                    mma16816_init(c1[0][0], afr[0][0], bfr[0], bfr[2], bA.x, bA.y);
                    mma16816_init(c1[0][1], afr[0][1], bfr[0], bfr[2], bA.x, bA.y);
                    mma16816_init(c1[1][0], afr[0][0], bfr[1], bfr[3], bB.x, bB.y);
                    mma16816_init(c1[1][1], afr[0][1], bfr[1], bfr[3], bB.x, bB.y);
                }
                #pragma unroll
                for (int kt = 1; kt < 3; kt++) {
                    uint32_t bfr[4];
                    ldsm_x4(bfr, sbase + SM_W0 + (hcj * 16 + (lane & 15)) * PITCH_W0
                                 + kt * 32 + ((lane >> 4) << 4));
                    mma16816(c1[0][0], afr[kt][0], bfr[0], bfr[2]);
                    mma16816(c1[0][1], afr[kt][1], bfr[0], bfr[2]);
                    mma16816(c1[1][0], afr[kt][0], bfr[1], bfr[3]);
                    mma16816(c1[1][1], afr[kt][1], bfr[1], bfr[3]);
                }

                uint32_t wfr[4];
                ldsm_x4(wfr, sbase + SM_W1 + (lane & 15) * PITCH_W1
                             + hcj * 32 + ((lane >> 4) << 4));
                #pragma unroll
                for (int mt = 0; mt < 2; mt++) {
                    uint32_t a2[4];
                    a2[0] = packrelu2(c1[0][mt][0], c1[0][mt][1]);
                    a2[1] = packrelu2(c1[0][mt][2], c1[0][mt][3]);
                    a2[2] = packrelu2(c1[1][mt][0], c1[1][mt][1]);
                    a2[3] = packrelu2(c1[1][mt][2], c1[1][mt][3]);
                    mma16816(c2[mt][0], a2, wfr[0], wfr[2]);
                    mma16816(c2[mt][1], a2, wfr[1], wfr[3]);
                }
            }

            // stage update: [ch][260] layout (conflict-free)
            float* s_upd = reinterpret_cast<float*>(smem + SM_UPD);
            #pragma unroll
            for (int mt = 0; mt < 2; mt++)
                #pragma unroll
                for (int n2 = 0; n2 < 2; n2++) {
                    const int ch = n2 * 8 + t * 2;
                    const int m  = m0 + mt * 16 + g;
                    s_upd[ch * UPD_PITCH + m]           = c2[mt][n2][0];
                    s_upd[(ch + 1) * UPD_PITCH + m]     = c2[mt][n2][1];
                    s_upd[ch * UPD_PITCH + m + 8]       = c2[mt][n2][2];
                    s_upd[(ch + 1) * UPD_PITCH + m + 8] = c2[mt][n2][3];
                }
        }
        __syncthreads();   // upd ready

        // ---------------- Phase 3: vectorized epilogue (x residual from ring) ----------------
        {
            const float* s_upd = reinterpret_cast<const float*>(smem + SM_UPD);
            const int q  = tid & 31;
            const int r  = (tid >> 5) & 1;
            const int cg = tid >> 6;
            const int h  = h0 + r;
            const int sr = h % 6;
            const int pw = wpix + q * 4;

            const float4 u4 = *reinterpret_cast<const float4*>(
                ru + ((size_t)bb * HN + h) * WN + pw);
            const float m0f = (u4.x > 0.5f) ? 1.0f : 0.0f;
            const float m1f = (u4.y > 0.5f) ? 1.0f : 0.0f;
            const float m2f = (u4.z > 0.5f) ? 1.0f : 0.0f;
            const float m3f = (u4.w > 0.5f) ? 1.0f : 0.0f;

            #pragma unroll
            for (int i = 0; i < 4; i++) {
                const int c = cg * 4 + i;
                const float4 up = *reinterpret_cast<const float4*>(
                    s_upd + c * UPD_PITCH + r * 128 + q * 4);
                const float4 xv = *reinterpret_cast<const float4*>(
                    ring + sr * RING_SLOT_F + c * 128 + q * 4);
                const size_t gi = (((size_t)bb * CN + c) * HN + h) * WN + pw;
                float4 o;
                o.x = xv.x + up.x * m0f;
                o.y = xv.y + up.y * m1f;
                o.z = xv.z + up.z * m2f;
                o.w = xv.w + up.w * m3f;
                *reinterpret_cast<float4*>(out + gi) = o;
            }
        }
        __syncthreads();   // ring reads done before overwriting slots

        // ---------------- Prefetch window(it+2)'s new rows ----------------
        if (it < NT - 2)
            prefetch2(x, smem, h0 + 5, bb, wpix, tid);
        CP_COMMIT();       // all threads commit every iteration (may be empty)
    }
}

// ============================================================
// Launch
// ============================================================
extern "C" void kernel_launch(void* const* d_in, const int* in_sizes, int n_in,
                              void* d_out, int out_size) {
    (void)in_sizes; (void)n_in; (void)out_size;
    const float* x  = (const float*)d_in[0];
    const float* w0 = (const float*)d_in[1];
    const float* b0 = (const float*)d_in[2];
    const float* w1 = (const float*)d_in[3];
    const float* ru = (const float*)d_in[4];
    float* out = (float*)d_out;

    static bool attr_set = false;
    if (!attr_set) {
        cudaFuncSetAttribute(ca_mlp_kernel,
                             cudaFuncAttributeMaxDynamicSharedMemorySize, SM_TOTAL);
        attr_set = true;
    }

    const int grid = BN * (HN / (2 * NT)) * (WN / TILE);   // 4 * 32 * 4 = 512
    ca_mlp_kernel<<<grid, 256, SM_TOTAL>>>(x, w0, b0, w1, ru, out);
}